// round 5
// baseline (speedup 1.0000x reference)
#include <cuda_runtime.h>
#include <math_constants.h>
#include <cstdint>

#define Bb   2
#define Nq   2048
#define Mk   4096
#define Dd   256
#define Hh   8
#define DK   32
#define KNNk 16

// ---------------- scratch ----------------
__device__ float g_Q[(size_t)Bb * Nq * Dd];
__device__ float g_K[(size_t)Bb * Mk * Dd];
__device__ float g_V[(size_t)Bb * Mk * Dd];
__device__ float g_X[(size_t)Bb * Nq * Dd];
__device__ float g_T[(size_t)Bb * Nq * Dd];
__device__ float g_Hb[(size_t)Bb * Nq * Dd];
__device__ int   g_idx[(size_t)Bb * Nq * KNNk];

// ---------------- tf32 helpers ----------------
__device__ __forceinline__ uint32_t f2tf32(float f) {
    uint32_t r;
    asm("cvt.rna.tf32.f32 %0, %1;" : "=r"(r) : "f"(f));
    return r;
}
__device__ __forceinline__ void mma_tf32(float c[4], uint32_t a0, uint32_t a1,
                                         uint32_t a2, uint32_t a3,
                                         uint32_t b0, uint32_t b1) {
    asm volatile(
        "mma.sync.aligned.m16n8k8.row.col.f32.tf32.tf32.f32 "
        "{%0,%1,%2,%3}, {%4,%5,%6,%7}, {%8,%9}, {%0,%1,%2,%3};"
        : "+f"(c[0]), "+f"(c[1]), "+f"(c[2]), "+f"(c[3])
        : "r"(a0), "r"(a1), "r"(a2), "r"(a3), "r"(b0), "r"(b1));
}

// ======================= tf32 GEMM 64x64 (double-buffered) =======================
// 256 threads, 8 warps: warp_m in {0,1} (32 rows), warp_n in {0..3} (16 cols).
__global__ __launch_bounds__(256) void gemm64_tf32_kernel(
    const float* __restrict__ A, const float* __restrict__ W,
    const float* __restrict__ bias, float* __restrict__ C)
{
    __shared__ uint32_t As[2][64][36];
    __shared__ uint32_t Ws[2][32][68];

    const int tid    = threadIdx.x;
    const int lane   = tid & 31;
    const int wid    = tid >> 5;
    const int warp_m = wid & 1;
    const int warp_n = wid >> 1;
    const int row0   = blockIdx.y * 64;
    const int col0   = blockIdx.x * 64;

    float acc[2][2][4];
#pragma unroll
    for (int mt = 0; mt < 2; mt++)
#pragma unroll
        for (int nt = 0; nt < 2; nt++)
#pragma unroll
            for (int i = 0; i < 4; i++) acc[mt][nt][i] = 0.f;

    float4 ra[2], rw[2];
#pragma unroll
    for (int u = 0; u < 2; u++) {
        int id = u * 256 + tid;
        ra[u] = *(const float4*)&A[(size_t)(row0 + (id >> 3)) * 256 + (id & 7) * 4];
        rw[u] = *(const float4*)&W[(size_t)(id >> 4) * 256 + col0 + (id & 15) * 4];
    }
    // store buffer 0
#pragma unroll
    for (int u = 0; u < 2; u++) {
        int id = u * 256 + tid;
        int r = id >> 3, kq = id & 7;
        As[0][r][kq * 4 + 0] = f2tf32(ra[u].x);
        As[0][r][kq * 4 + 1] = f2tf32(ra[u].y);
        As[0][r][kq * 4 + 2] = f2tf32(ra[u].z);
        As[0][r][kq * 4 + 3] = f2tf32(ra[u].w);
        int k = id >> 4, nq = id & 15;
        Ws[0][k][nq * 4 + 0] = f2tf32(rw[u].x);
        Ws[0][k][nq * 4 + 1] = f2tf32(rw[u].y);
        Ws[0][k][nq * 4 + 2] = f2tf32(rw[u].z);
        Ws[0][k][nq * 4 + 3] = f2tf32(rw[u].w);
    }
    __syncthreads();

    for (int it = 0; it < 8; it++) {
        const int cur = it & 1;
        if (it < 7) {
            const int k0n = (it + 1) * 32;
#pragma unroll
            for (int u = 0; u < 2; u++) {
                int id = u * 256 + tid;
                ra[u] = *(const float4*)&A[(size_t)(row0 + (id >> 3)) * 256 + k0n + (id & 7) * 4];
                rw[u] = *(const float4*)&W[(size_t)(k0n + (id >> 4)) * 256 + col0 + (id & 15) * 4];
            }
        }
#pragma unroll
        for (int kk = 0; kk < 4; kk++) {
            const int ko = kk * 8;
            const int kc = ko + (lane & 3);
            uint32_t af[2][4];
#pragma unroll
            for (int mt = 0; mt < 2; mt++) {
                const int mb = warp_m * 32 + mt * 16 + (lane >> 2);
                af[mt][0] = As[cur][mb][kc];
                af[mt][1] = As[cur][mb + 8][kc];
                af[mt][2] = As[cur][mb][kc + 4];
                af[mt][3] = As[cur][mb + 8][kc + 4];
            }
#pragma unroll
            for (int nt = 0; nt < 2; nt++) {
                const int nb = warp_n * 16 + nt * 8 + (lane >> 2);
                uint32_t b0 = Ws[cur][kc][nb];
                uint32_t b1 = Ws[cur][kc + 4][nb];
#pragma unroll
                for (int mt = 0; mt < 2; mt++)
                    mma_tf32(acc[mt][nt], af[mt][0], af[mt][1], af[mt][2], af[mt][3], b0, b1);
            }
        }
        if (it < 7) {
            const int nxt = cur ^ 1;
#pragma unroll
            for (int u = 0; u < 2; u++) {
                int id = u * 256 + tid;
                int r = id >> 3, kq = id & 7;
                As[nxt][r][kq * 4 + 0] = f2tf32(ra[u].x);
                As[nxt][r][kq * 4 + 1] = f2tf32(ra[u].y);
                As[nxt][r][kq * 4 + 2] = f2tf32(ra[u].z);
                As[nxt][r][kq * 4 + 3] = f2tf32(ra[u].w);
                int k = id >> 4, nq = id & 15;
                Ws[nxt][k][nq * 4 + 0] = f2tf32(rw[u].x);
                Ws[nxt][k][nq * 4 + 1] = f2tf32(rw[u].y);
                Ws[nxt][k][nq * 4 + 2] = f2tf32(rw[u].z);
                Ws[nxt][k][nq * 4 + 3] = f2tf32(rw[u].w);
            }
            __syncthreads();
        }
    }

#pragma unroll
    for (int nt = 0; nt < 2; nt++) {
        const int col = col0 + warp_n * 16 + nt * 8 + (lane & 3) * 2;
        const float b0 = bias[col], b1 = bias[col + 1];
#pragma unroll
        for (int mt = 0; mt < 2; mt++) {
            const int row = row0 + warp_m * 32 + mt * 16 + (lane >> 2);
            *(float2*)&C[(size_t)row * 256 + col] =
                make_float2(acc[mt][nt][0] + b0, acc[mt][nt][1] + b1);
            *(float2*)&C[(size_t)(row + 8) * 256 + col] =
                make_float2(acc[mt][nt][2] + b0, acc[mt][nt][3] + b1);
        }
    }
}

// ======================= dual tf32 GEMM 128x64 (double-buffered, dynamic smem) ===========
__global__ __launch_bounds__(256) void gemm_tf32_dual_kernel(
    const float* __restrict__ A,
    const float* __restrict__ WK, const float* __restrict__ bK,
    const float* __restrict__ WV, const float* __restrict__ bV,
    float* __restrict__ CK, float* __restrict__ CV)
{
    extern __shared__ uint32_t smem[];
    uint32_t (*As)[128][36]  = (uint32_t(*)[128][36])smem;                    // 2*128*36
    uint32_t (*WsK)[32][68]  = (uint32_t(*)[32][68])(smem + 2 * 128 * 36);    // 2*32*68
    uint32_t (*WsV)[32][68]  = (uint32_t(*)[32][68])(smem + 2 * 128 * 36 + 2 * 32 * 68);

    const int tid    = threadIdx.x;
    const int lane   = tid & 31;
    const int wid    = tid >> 5;
    const int warp_m = wid & 3;
    const int warp_n = wid >> 2;
    const int row0   = blockIdx.y * 128;
    const int col0   = blockIdx.x * 64;

    float accK[2][4][4], accV[2][4][4];
#pragma unroll
    for (int mt = 0; mt < 2; mt++)
#pragma unroll
        for (int nt = 0; nt < 4; nt++)
#pragma unroll
            for (int i = 0; i < 4; i++) { accK[mt][nt][i] = 0.f; accV[mt][nt][i] = 0.f; }

    float4 ra[4], rk[2], rv[2];
#pragma unroll
    for (int u = 0; u < 4; u++) {
        int id = u * 256 + tid;
        ra[u] = *(const float4*)&A[(size_t)(row0 + (id >> 3)) * 256 + (id & 7) * 4];
    }
#pragma unroll
    for (int u = 0; u < 2; u++) {
        int id = u * 256 + tid;
        rk[u] = *(const float4*)&WK[(size_t)(id >> 4) * 256 + col0 + (id & 15) * 4];
        rv[u] = *(const float4*)&WV[(size_t)(id >> 4) * 256 + col0 + (id & 15) * 4];
    }
#pragma unroll
    for (int u = 0; u < 4; u++) {
        int id = u * 256 + tid, r = id >> 3, kq = id & 7;
        As[0][r][kq * 4 + 0] = f2tf32(ra[u].x);
        As[0][r][kq * 4 + 1] = f2tf32(ra[u].y);
        As[0][r][kq * 4 + 2] = f2tf32(ra[u].z);
        As[0][r][kq * 4 + 3] = f2tf32(ra[u].w);
    }
#pragma unroll
    for (int u = 0; u < 2; u++) {
        int id = u * 256 + tid, k = id >> 4, nq = id & 15;
        WsK[0][k][nq * 4 + 0] = f2tf32(rk[u].x);
        WsK[0][k][nq * 4 + 1] = f2tf32(rk[u].y);
        WsK[0][k][nq * 4 + 2] = f2tf32(rk[u].z);
        WsK[0][k][nq * 4 + 3] = f2tf32(rk[u].w);
        WsV[0][k][nq * 4 + 0] = f2tf32(rv[u].x);
        WsV[0][k][nq * 4 + 1] = f2tf32(rv[u].y);
        WsV[0][k][nq * 4 + 2] = f2tf32(rv[u].z);
        WsV[0][k][nq * 4 + 3] = f2tf32(rv[u].w);
    }
    __syncthreads();

    for (int it = 0; it < 8; it++) {
        const int cur = it & 1;
        if (it < 7) {
            const int k0n = (it + 1) * 32;
#pragma unroll
            for (int u = 0; u < 4; u++) {
                int id = u * 256 + tid;
                ra[u] = *(const float4*)&A[(size_t)(row0 + (id >> 3)) * 256 + k0n + (id & 7) * 4];
            }
#pragma unroll
            for (int u = 0; u < 2; u++) {
                int id = u * 256 + tid;
                rk[u] = *(const float4*)&WK[(size_t)(k0n + (id >> 4)) * 256 + col0 + (id & 15) * 4];
                rv[u] = *(const float4*)&WV[(size_t)(k0n + (id >> 4)) * 256 + col0 + (id & 15) * 4];
            }
        }
#pragma unroll
        for (int kk = 0; kk < 4; kk++) {
            const int ko = kk * 8;
            const int kc = ko + (lane & 3);
            uint32_t af[2][4];
#pragma unroll
            for (int mt = 0; mt < 2; mt++) {
                const int mb = warp_m * 32 + mt * 16 + (lane >> 2);
                af[mt][0] = As[cur][mb][kc];
                af[mt][1] = As[cur][mb + 8][kc];
                af[mt][2] = As[cur][mb][kc + 4];
                af[mt][3] = As[cur][mb + 8][kc + 4];
            }
#pragma unroll
            for (int nt = 0; nt < 4; nt++) {
                const int nb = warp_n * 32 + nt * 8 + (lane >> 2);
                uint32_t bk0 = WsK[cur][kc][nb], bk1 = WsK[cur][kc + 4][nb];
                uint32_t bv0 = WsV[cur][kc][nb], bv1 = WsV[cur][kc + 4][nb];
#pragma unroll
                for (int mt = 0; mt < 2; mt++) {
                    mma_tf32(accK[mt][nt], af[mt][0], af[mt][1], af[mt][2], af[mt][3], bk0, bk1);
                    mma_tf32(accV[mt][nt], af[mt][0], af[mt][1], af[mt][2], af[mt][3], bv0, bv1);
                }
            }
        }
        if (it < 7) {
            const int nxt = cur ^ 1;
#pragma unroll
            for (int u = 0; u < 4; u++) {
                int id = u * 256 + tid, r = id >> 3, kq = id & 7;
                As[nxt][r][kq * 4 + 0] = f2tf32(ra[u].x);
                As[nxt][r][kq * 4 + 1] = f2tf32(ra[u].y);
                As[nxt][r][kq * 4 + 2] = f2tf32(ra[u].z);
                As[nxt][r][kq * 4 + 3] = f2tf32(ra[u].w);
            }
#pragma unroll
            for (int u = 0; u < 2; u++) {
                int id = u * 256 + tid, k = id >> 4, nq = id & 15;
                WsK[nxt][k][nq * 4 + 0] = f2tf32(rk[u].x);
                WsK[nxt][k][nq * 4 + 1] = f2tf32(rk[u].y);
                WsK[nxt][k][nq * 4 + 2] = f2tf32(rk[u].z);
                WsK[nxt][k][nq * 4 + 3] = f2tf32(rk[u].w);
                WsV[nxt][k][nq * 4 + 0] = f2tf32(rv[u].x);
                WsV[nxt][k][nq * 4 + 1] = f2tf32(rv[u].y);
                WsV[nxt][k][nq * 4 + 2] = f2tf32(rv[u].z);
                WsV[nxt][k][nq * 4 + 3] = f2tf32(rv[u].w);
            }
            __syncthreads();
        }
    }

#pragma unroll
    for (int nt = 0; nt < 4; nt++) {
        const int col = col0 + warp_n * 32 + nt * 8 + (lane & 3) * 2;
        const float bk0 = bK[col], bk1 = bK[col + 1];
        const float bv0 = bV[col], bv1 = bV[col + 1];
#pragma unroll
        for (int mt = 0; mt < 2; mt++) {
            const int row = row0 + warp_m * 32 + mt * 16 + (lane >> 2);
            *(float2*)&CK[(size_t)row * 256 + col] =
                make_float2(accK[mt][nt][0] + bk0, accK[mt][nt][1] + bk1);
            *(float2*)&CK[(size_t)(row + 8) * 256 + col] =
                make_float2(accK[mt][nt][2] + bk0, accK[mt][nt][3] + bk1);
            *(float2*)&CV[(size_t)row * 256 + col] =
                make_float2(accV[mt][nt][0] + bv0, accV[mt][nt][1] + bv1);
            *(float2*)&CV[(size_t)(row + 8) * 256 + col] =
                make_float2(accV[mt][nt][2] + bv0, accV[mt][nt][3] + bv1);
        }
    }
}

// ======================= kNN: register-resident top-16 =======================
__global__ __launch_bounds__(128) void knn_kernel(
    const float* __restrict__ src, const float* __restrict__ tgt,
    int* __restrict__ knn_idx)
{
    __shared__ float lmin[128];
    __shared__ int   lidx[128];
    __shared__ int   s_win;

    const int qid = blockIdx.x;
    const int b   = qid / Nq;
    const int tid = threadIdx.x;

    const float qx = src[(size_t)qid * 3 + 0];
    const float qy = src[(size_t)qid * 3 + 1];
    const float qz = src[(size_t)qid * 3 + 2];
    const float qq = qx * qx + qy * qy + qz * qz;
    const float* tb = tgt + (size_t)b * Mk * 3;

    float d[32];
    float bm = CUDART_INF_F;
    int   bi = Mk;
#pragma unroll
    for (int i = 0; i < 32; i++) {
        const int m = i * 128 + tid;
        float x = tb[(size_t)m * 3 + 0];
        float y = tb[(size_t)m * 3 + 1];
        float z = tb[(size_t)m * 3 + 2];
        float sq = fmaxf(qq + (x * x + y * y + z * z) - 2.f * (qx * x + qy * y + qz * z), 0.f);
        d[i] = sq;
        if (sq < bm) { bm = sq; bi = m; }
    }
    lmin[tid] = bm; lidx[tid] = bi;
    __syncthreads();

    uint32_t mask = 0;
    for (int it = 0; it < KNNk; it++) {
        if (tid < 32) {
            float v = lmin[tid]; int ix = lidx[tid];
#pragma unroll
            for (int j = 32; j < 128; j += 32) {
                float v2 = lmin[tid + j]; int i2 = lidx[tid + j];
                if (v2 < v || (v2 == v && i2 < ix)) { v = v2; ix = i2; }
            }
#pragma unroll
            for (int o = 16; o > 0; o >>= 1) {
                float v2 = __shfl_xor_sync(0xFFFFFFFFu, v, o);
                int   i2 = __shfl_xor_sync(0xFFFFFFFFu, ix, o);
                if (v2 < v || (v2 == v && i2 < ix)) { v = v2; ix = i2; }
            }
            if (tid == 0) {
                s_win = ix;
                knn_idx[(size_t)qid * KNNk + it] = ix;
            }
        }
        __syncthreads();
        if (it < KNNk - 1) {
            const int win = s_win;
            if (tid == (win & 127)) {
                mask |= 1u << (win >> 7);
                float nb = CUDART_INF_F; int ni = Mk;
#pragma unroll
                for (int i = 0; i < 32; i++) {
                    if (!(mask & (1u << i)) && d[i] < nb) { nb = d[i]; ni = i * 128 + tid; }
                }
                lmin[tid] = nb; lidx[tid] = ni;
            }
            __syncthreads();
        }
    }
}

// ======================= sparse attention =======================
#define KSTRIDE 261

__global__ __launch_bounds__(256) void attn_kernel(const float* __restrict__ src_fea,
                                                   float* __restrict__ avg_attn)
{
    __shared__ int   sidx[KNNk];
    __shared__ float sq[Dd];
    __shared__ float sattn[Hh][KNNk];
    __shared__ float sK[KNNk][KSTRIDE];

    const int qid = blockIdx.x;
    const int b   = qid / Nq;
    const int tid = threadIdx.x;

    if (tid < KNNk) sidx[tid] = g_idx[(size_t)qid * KNNk + tid];
    sq[tid] = g_Q[(size_t)qid * Dd + tid];
    __syncthreads();

    {
        const int c4 = tid & 63;
        const int rg = tid >> 6;
#pragma unroll
        for (int it = 0; it < 4; it++) {
            const int r = rg + it * 4;
            float4 kv = *(const float4*)&g_K[((size_t)b * Mk + sidx[r]) * Dd + c4 * 4];
            sK[r][c4 * 4 + 0] = kv.x; sK[r][c4 * 4 + 1] = kv.y;
            sK[r][c4 * 4 + 2] = kv.z; sK[r][c4 * 4 + 3] = kv.w;
        }
    }
    __syncthreads();

    if (tid < Hh * KNNk) {
        const int h = tid >> 4;
        const int j = tid & 15;
        float s = 0.f;
#pragma unroll
        for (int d = 0; d < DK; d++) s += sq[h * DK + d] * sK[j][h * DK + d];
        s *= 0.17677669529663687f;

        float m = s;
#pragma unroll
        for (int o = 8; o > 0; o >>= 1) m = fmaxf(m, __shfl_xor_sync(0xFFFFFFFFu, m, o));
        float e = __expf(s - m);
        float sum = e;
#pragma unroll
        for (int o = 8; o > 0; o >>= 1) sum += __shfl_xor_sync(0xFFFFFFFFu, sum, o);
        sattn[h][j] = e / sum;
    }
    __syncthreads();

    {
        const int d = tid;
        const int h = d >> 5;
        const float* vb = &g_V[(size_t)b * Mk * Dd + d];
        float o = 0.f;
#pragma unroll
        for (int j = 0; j < KNNk; j++)
            o += sattn[h][j] * vb[(size_t)sidx[j] * Dd];
        g_X[(size_t)qid * Dd + d] = o + src_fea[(size_t)qid * Dd + d];
    }

    float* rowp = avg_attn + (size_t)qid * Mk;
    float4 z = make_float4(0.f, 0.f, 0.f, 0.f);
#pragma unroll
    for (int i = 0; i < 4; i++) ((float4*)rowp)[tid + i * 256] = z;
    __syncthreads();
    if (tid < KNNk) {
        float a = 0.f;
#pragma unroll
        for (int h = 0; h < Hh; h++) a += sattn[h][tid];
        rowp[sidx[tid]] = a * 0.125f;
    }
}

// ======================= LayerNorm + ReLU =======================
__global__ __launch_bounds__(256) void ln_relu_kernel(
    const float* __restrict__ T, const float* __restrict__ gam,
    const float* __restrict__ bet, float* __restrict__ Hb)
{
    __shared__ float red[8];
    const int row = blockIdx.x;
    const int tid = threadIdx.x;

    float x = T[(size_t)row * Dd + tid];

    float s = x;
#pragma unroll
    for (int o = 16; o > 0; o >>= 1) s += __shfl_xor_sync(0xFFFFFFFFu, s, o);
    if ((tid & 31) == 0) red[tid >> 5] = s;
    __syncthreads();
    float mu = (red[0] + red[1] + red[2] + red[3] + red[4] + red[5] + red[6] + red[7]) * (1.f / 256.f);
    __syncthreads();

    float dx = x - mu;
    float s2 = dx * dx;
#pragma unroll
    for (int o = 16; o > 0; o >>= 1) s2 += __shfl_xor_sync(0xFFFFFFFFu, s2, o);
    if ((tid & 31) == 0) red[tid >> 5] = s2;
    __syncthreads();
    float var = (red[0] + red[1] + red[2] + red[3] + red[4] + red[5] + red[6] + red[7]) * (1.f / 256.f);

    float y = dx * rsqrtf(var + 1e-5f) * gam[tid] + bet[tid];
    Hb[(size_t)row * Dd + tid] = fmaxf(y, 0.f);
}

// ======================= launch =======================
extern "C" void kernel_launch(void* const* d_in, const int* in_sizes, int n_in,
                              void* d_out, int out_size)
{
    const float* src     = (const float*)d_in[0];
    const float* tgt     = (const float*)d_in[1];
    const float* src_fea = (const float*)d_in[2];
    const float* tgt_fea = (const float*)d_in[3];
    const float* Wq  = (const float*)d_in[4];  const float* bq  = (const float*)d_in[5];
    const float* Wk  = (const float*)d_in[6];  const float* bk  = (const float*)d_in[7];
    const float* Wv  = (const float*)d_in[8];  const float* bv  = (const float*)d_in[9];
    const float* Wo1 = (const float*)d_in[10]; const float* bo1 = (const float*)d_in[11];
    const float* lng = (const float*)d_in[12]; const float* lnb = (const float*)d_in[13];
    const float* Wo2 = (const float*)d_in[14]; const float* bo2 = (const float*)d_in[15];

    float* outp = (float*)d_out;
    float* upd  = outp;
    float* avg  = outp + (size_t)Bb * Nq * Dd;

    float *pQ, *pK, *pV, *pX, *pT, *pHb; int* pIdx;
    cudaGetSymbolAddress((void**)&pQ,  g_Q);
    cudaGetSymbolAddress((void**)&pK,  g_K);
    cudaGetSymbolAddress((void**)&pV,  g_V);
    cudaGetSymbolAddress((void**)&pX,  g_X);
    cudaGetSymbolAddress((void**)&pT,  g_T);
    cudaGetSymbolAddress((void**)&pHb, g_Hb);
    cudaGetSymbolAddress((void**)&pIdx, g_idx);

    const int dual_smem = (2 * 128 * 36 + 4 * 32 * 68) * 4;  // 71680 B
    cudaFuncSetAttribute(gemm_tf32_dual_kernel,
                         cudaFuncAttributeMaxDynamicSharedMemorySize, dual_smem);

    knn_kernel<<<Bb * Nq, 128>>>(src, tgt, pIdx);

    gemm64_tf32_kernel<<<dim3(4, (Bb * Nq) / 64), 256>>>(src_fea, Wq, bq, pQ);
    gemm_tf32_dual_kernel<<<dim3(4, (Bb * Mk) / 128), 256, dual_smem>>>(
        tgt_fea, Wk, bk, Wv, bv, pK, pV);

    attn_kernel<<<Bb * Nq, 256>>>(src_fea, avg);

    gemm64_tf32_kernel<<<dim3(4, (Bb * Nq) / 64), 256>>>(pX, Wo1, bo1, pT);
    ln_relu_kernel<<<Bb * Nq, 256>>>(pT, lng, lnb, pHb);
    gemm64_tf32_kernel<<<dim3(4, (Bb * Nq) / 64), 256>>>(pHb, Wo2, bo2, upd);
}